// round 5
// baseline (speedup 1.0000x reference)
#include <cuda_runtime.h>
#include <cstdint>

#define N0    512000
#define IN_F  128
#define HID   256
#define OUT_F 64
#define NN1   20480
#define NN2   2048
#define NE1   512000
#define NE2   20480
#define EPSV  1e-4f

// ---------------- device scratch ----------------
__device__ float    g_alpha1[N0];
__device__ uint4    g_mask1[N0];      // word q bit L = col 4L+q
__device__ unsigned g_cnt1[NN1];
__device__ unsigned g_off1[NN1 + 1];
__device__ unsigned g_cur1[NN1];
__device__ int      g_srcs1[NE1];
__device__ float    g_agg1[NN1 * IN_F];
__device__ float    g_alpha2[NN1];
__device__ unsigned g_mask2[NN1 * 8]; // word q bit b = col 32q+b
__device__ unsigned g_cnt2[NN2];
__device__ unsigned g_off2[NN2 + 1];
__device__ unsigned g_cur2[NN2];
__device__ int      g_srcs2[NE2];
__device__ float    g_bt1[IN_F * HID];  // w_hat_rel1 transposed [k=128][n=256]
__device__ float    g_mroot1[HID];
__device__ uint4    g_wmask1[HID];      // word q bit L = col 4L+q (of 128 in-cols)
__device__ float    g_bsum1[HID];
__device__ float    g_bt2[HID * OUT_F]; // [256][64]
__device__ float    g_mroot2[OUT_F];
__device__ unsigned g_wmask2[OUT_F * 8];// word q bit L = col 32q+L (of 256 in-cols)
__device__ float    g_bsum2[OUT_F];

// ---------------- helpers ----------------
__device__ __forceinline__ float warp_sum(float v) {
#pragma unroll
    for (int o = 16; o; o >>= 1) v += __shfl_xor_sync(0xffffffffu, v, o);
    return v;
}
__device__ __forceinline__ float warp_max(float v) {
#pragma unroll
    for (int o = 16; o; o >>= 1) v = fmaxf(v, __shfl_xor_sync(0xffffffffu, v, o));
    return v;
}
__device__ __forceinline__ unsigned long long bcast2(float a) {
    unsigned long long r;
    asm("mov.b64 %0, {%1, %1};" : "=l"(r) : "f"(a));
    return r;
}
__device__ __forceinline__ void fma2(unsigned long long& c, unsigned long long a, unsigned long long b) {
    asm("fma.rn.f32x2 %0, %1, %2, %0;" : "+l"(c) : "l"(a), "l"(b));
}
__device__ __forceinline__ void unpack2(unsigned long long v, float& lo, float& hi) {
    asm("mov.b64 {%0, %1}, %2;" : "=f"(lo), "=f"(hi) : "l"(v));
}
__device__ __forceinline__ int popc4(uint4 a, uint4 b) {
    return __popc(a.x ^ b.x) + __popc(a.y ^ b.y) + __popc(a.z ^ b.z) + __popc(a.w ^ b.w);
}

// ---------------- prep: weights + counter zero ----------------
__global__ __launch_bounds__(128) void prep_zero(
    const float* __restrict__ wr1, const float* __restrict__ wroot1,
    const float* __restrict__ wr2, const float* __restrict__ wroot2,
    const float* __restrict__ brel1, const float* __restrict__ broot1,
    const float* __restrict__ brel2, const float* __restrict__ broot2)
{
    int t = blockIdx.x * 128 + threadIdx.x;
    g_cnt1[t] = 0u;
    if (t < NN2) g_cnt2[t] = 0u;
    if (t < HID) g_bsum1[t] = brel1[t] + broot1[t];
    if (t < OUT_F) g_bsum2[t] = brel2[t] + broot2[t];

    int w = t >> 5;
    int L = threadIdx.x & 31;
    if (w < HID) {                      // rel1 -> fp32 w_hat transposed
        int k = w;
        float4 v = *(const float4*)(wr1 + (size_t)k * IN_F + 4 * L);
        float s = warp_sum(fabsf(v.x) + fabsf(v.y) + fabsf(v.z) + fabsf(v.w));
        float m = s * (1.f / IN_F);
        float vv[4] = {v.x, v.y, v.z, v.w};
#pragma unroll
        for (int q = 0; q < 4; q++) {
            int j = 4 * L + q;
            g_bt1[j * HID + k] = vv[q] > 0.f ? m : (vv[q] < 0.f ? -m : 0.f);
        }
    } else if (w < 2 * HID) {           // root1 -> masks + mroot
        int k = w - HID;
        float4 v = *(const float4*)(wroot1 + (size_t)k * IN_F + 4 * L);
        float s = warp_sum(fabsf(v.x) + fabsf(v.y) + fabsf(v.z) + fabsf(v.w));
        unsigned b0 = __ballot_sync(0xffffffffu, v.x > 0.f);
        unsigned b1 = __ballot_sync(0xffffffffu, v.y > 0.f);
        unsigned b2 = __ballot_sync(0xffffffffu, v.z > 0.f);
        unsigned b3 = __ballot_sync(0xffffffffu, v.w > 0.f);
        if (L == 0) {
            g_mroot1[k] = s * (1.f / IN_F);
            g_wmask1[k] = make_uint4(b0, b1, b2, b3);
        }
    } else if (w < 2 * HID + OUT_F) {   // rel2 -> fp32 bt2
        int k = w - 2 * HID;
        float4 u = *(const float4*)(wr2 + (size_t)k * HID + 8 * L);
        float4 v = *(const float4*)(wr2 + (size_t)k * HID + 8 * L + 4);
        float s = warp_sum(fabsf(u.x) + fabsf(u.y) + fabsf(u.z) + fabsf(u.w) +
                           fabsf(v.x) + fabsf(v.y) + fabsf(v.z) + fabsf(v.w));
        float m = s * (1.f / HID);
        float vv[8] = {u.x, u.y, u.z, u.w, v.x, v.y, v.z, v.w};
#pragma unroll
        for (int q = 0; q < 8; q++) {
            int j = 8 * L + q;
            g_bt2[j * OUT_F + k] = vv[q] > 0.f ? m : (vv[q] < 0.f ? -m : 0.f);
        }
    } else if (w < 2 * HID + 2 * OUT_F) { // root2 -> masks: word q bit L = col 32q+L
        int k = w - 2 * HID - OUT_F;
        float s = 0.f;
        unsigned b[8];
#pragma unroll
        for (int q = 0; q < 8; q++) {
            float f = wroot2[(size_t)k * HID + 32 * q + L];
            s += fabsf(f);
            b[q] = __ballot_sync(0xffffffffu, f > 0.f);
        }
        s = warp_sum(s);
        if (L == 0) {
            g_mroot2[k] = s * (1.f / HID);
#pragma unroll
            for (int q = 0; q < 8; q++) g_wmask2[k * 8 + q] = b[q];
        }
    }
}

// ---------------- binact1 + hist (hist blocks first, 4 edges/thread) --------
#define HB 260
__global__ __launch_bounds__(512) void binact1hist_kernel(
    const float* __restrict__ x, const int* __restrict__ dst1,
    const int* __restrict__ dst2)
{
    unsigned bid = blockIdx.x;
    if (bid < HB) {
        unsigned t = bid * 512u + threadIdx.x;
        if (t < NE1 / 4) {
            int4 d = ((const int4*)dst1)[t];
            atomicAdd(&g_cnt1[d.x], 1u); atomicAdd(&g_cnt1[d.y], 1u);
            atomicAdd(&g_cnt1[d.z], 1u); atomicAdd(&g_cnt1[d.w], 1u);
        } else {
            unsigned j = t - NE1 / 4;
            if (j < NE2 / 4) {
                int4 d = ((const int4*)dst2)[j];
                atomicAdd(&g_cnt2[d.x], 1u); atomicAdd(&g_cnt2[d.y], 1u);
                atomicAdd(&g_cnt2[d.z], 1u); atomicAdd(&g_cnt2[d.w], 1u);
            }
        }
        return;
    }
    int row = (bid - HB) * 16 + (threadIdx.x >> 5);
    int L = threadIdx.x & 31;
    float4 v = *(const float4*)(x + (size_t)row * IN_F + 4 * L);
    float s = v.x + v.y + v.z + v.w;
    float sq = fmaf(v.x, v.x, fmaf(v.y, v.y, fmaf(v.z, v.z, v.w * v.w)));
    s = warp_sum(s);
    sq = warp_sum(sq);
    float mu = s * (1.f / 128.f);
    float var = (sq - 128.f * mu * mu) * (1.f / 127.f);
    float sd = sqrtf(fmaxf(var, 0.f));
    float d0 = v.x - mu, d1 = v.y - mu, d2 = v.z - mu, d3 = v.w - mu;
    float l1 = warp_sum(fabsf(d0) + fabsf(d1) + fabsf(d2) + fabsf(d3));
    float a = (l1 * (1.f / 128.f)) / (sd + EPSV);
    unsigned b0 = __ballot_sync(0xffffffffu, d0 > 0.f);
    unsigned b1 = __ballot_sync(0xffffffffu, d1 > 0.f);
    unsigned b2 = __ballot_sync(0xffffffffu, d2 > 0.f);
    unsigned b3 = __ballot_sync(0xffffffffu, d3 > 0.f);
    if (L == 0) {
        g_alpha1[row] = a;
        g_mask1[row] = make_uint4(b0, b1, b2, b3);
    }
}

// ---------------- scan (both layers) ----------------
__global__ __launch_bounds__(1024) void scan12_kernel() {
    int layer = blockIdx.x;
    const unsigned* cnt = layer ? g_cnt2 : g_cnt1;
    unsigned* off = layer ? g_off2 : g_off1;
    unsigned* cur = layer ? g_cur2 : g_cur1;
    int n = layer ? NN2 : NN1;
    int per = n >> 10;
    int t = threadIdx.x;
    int s0 = t * per;
    unsigned tot = 0;
    for (int i = 0; i < per; i++) tot += cnt[s0 + i];
    unsigned ws = tot;
#pragma unroll
    for (int o = 1; o < 32; o <<= 1) {
        unsigned u = __shfl_up_sync(0xffffffffu, ws, o);
        if ((t & 31) >= o) ws += u;
    }
    __shared__ unsigned wsum[32];
    if ((t & 31) == 31) wsum[t >> 5] = ws;
    __syncthreads();
    if (t < 32) {
        unsigned v2 = wsum[t], sc = v2;
#pragma unroll
        for (int o = 1; o < 32; o <<= 1) {
            unsigned u = __shfl_up_sync(0xffffffffu, sc, o);
            if (t >= o) sc += u;
        }
        wsum[t] = sc - v2;
    }
    __syncthreads();
    unsigned run = wsum[t >> 5] + ws - tot;
    for (int i = 0; i < per; i++) {
        unsigned c = cnt[s0 + i];
        off[s0 + i] = run;
        cur[s0 + i] = run;
        run += c;
    }
    if (t == 1023) off[n] = run;
}

// ---------------- placement (4 edges/thread) ----------------
__global__ __launch_bounds__(512) void place12_kernel(
    const int* __restrict__ dst1, const int* __restrict__ src1,
    const int* __restrict__ dst2, const int* __restrict__ src2)
{
    unsigned t = blockIdx.x * 512u + threadIdx.x;
    if (t < NE1 / 4) {
        int4 d = ((const int4*)dst1)[t];
        int4 s = ((const int4*)src1)[t];
        g_srcs1[atomicAdd(&g_cur1[d.x], 1u)] = s.x;
        g_srcs1[atomicAdd(&g_cur1[d.y], 1u)] = s.y;
        g_srcs1[atomicAdd(&g_cur1[d.z], 1u)] = s.z;
        g_srcs1[atomicAdd(&g_cur1[d.w], 1u)] = s.w;
    } else {
        unsigned j = t - NE1 / 4;
        if (j < NE2 / 4) {
            int4 d = ((const int4*)dst2)[j];
            int4 s = ((const int4*)src2)[j];
            g_srcs2[atomicAdd(&g_cur2[d.x], 1u)] = s.x;
            g_srcs2[atomicAdd(&g_cur2[d.y], 1u)] = s.y;
            g_srcs2[atomicAdd(&g_cur2[d.z], 1u)] = s.z;
            g_srcs2[atomicAdd(&g_cur2[d.w], 1u)] = s.w;
        }
    }
}

// ---------------- layer-1 aggregation ----------------
__global__ __launch_bounds__(256) void agg1_kernel() {
    int d = (blockIdx.x * 256 + threadIdx.x) >> 5;
    int L = threadIdx.x & 31;
    unsigned beg = g_off1[d], end = g_off1[d + 1];
    float a0 = 0.f, a1 = 0.f, a2 = 0.f, a3 = 0.f;
    for (unsigned base = beg; base < end; base += 32u) {
        unsigned e = base + L;
        float al = 0.f;
        uint4 m = make_uint4(0u, 0u, 0u, 0u);
        if (e < end) {
            int s = g_srcs1[e];
            al = g_alpha1[s];
            m = g_mask1[s];
        }
        unsigned n = min(32u, end - base);
        for (unsigned t = 0; t < n; t++) {
            float av = __shfl_sync(0xffffffffu, al, t);
            unsigned mx = __shfl_sync(0xffffffffu, m.x, t);
            unsigned my = __shfl_sync(0xffffffffu, m.y, t);
            unsigned mz = __shfl_sync(0xffffffffu, m.z, t);
            unsigned mw = __shfl_sync(0xffffffffu, m.w, t);
            a0 += ((mx >> L) & 1u) ? av : -av;
            a1 += ((my >> L) & 1u) ? av : -av;
            a2 += ((mz >> L) & 1u) ? av : -av;
            a3 += ((mw >> L) & 1u) ? av : -av;
        }
    }
    unsigned c = end - beg;
    float inv = 1.f / (float)(c == 0u ? 1u : c);
    *(float4*)(g_agg1 + (size_t)d * IN_F + 4 * L) =
        make_float4(a0 * inv, a1 * inv, a2 * inv, a3 * inv);
}

// ---------------- gemm1 + root + bias + relu + binact2 (no spills) ---------
// 512 threads; tile M=64 x N=256; warp pair p=w>>1 -> rows 8p..8p+7,
// half h=w&1, lane L -> cols h*128+4L..+3. acc = 16 ULL (32 regs).
#define GBK 16
__global__ __launch_bounds__(512, 1) void gemm1_fused_kernel() {
    __shared__ float As[GBK][72];     // k-major
    __shared__ float Bs[GBK][264];
    __shared__ float2 redS[64][2];
    __shared__ float  redL[64][2];
    __shared__ unsigned smask[64][8];
    int tid = threadIdx.x;
    int w = tid >> 5, L = tid & 31;
    int p = w >> 1, h = w & 1;
    int bm = blockIdx.x * 64;
    smask[tid >> 3][tid & 7] = 0u;

    unsigned long long acc[8][2];
#pragma unroll
    for (int i = 0; i < 8; i++) { acc[i][0] = 0ull; acc[i][1] = 0ull; }

    for (int k0 = 0; k0 < IN_F; k0 += GBK) {
        if (tid < 256) {   // A: 64 rows x 16 k
            int row = tid >> 2, kq = tid & 3;
            float4 v = *(const float4*)(g_agg1 + (size_t)(bm + row) * IN_F + k0 + 4 * kq);
            As[kq * 4 + 0][row] = v.x;
            As[kq * 4 + 1][row] = v.y;
            As[kq * 4 + 2][row] = v.z;
            As[kq * 4 + 3][row] = v.w;
        }
#pragma unroll
        for (int r = 0; r < 2; r++) {  // B: 16 k x 256 cols
            int g = tid + r * 512;
            int kk = g >> 6, n4 = g & 63;
            *(float4*)&Bs[kk][4 * n4] =
                *(const float4*)(g_bt1 + (size_t)(k0 + kk) * HID + 4 * n4);
        }
        __syncthreads();
#pragma unroll
        for (int kk = 0; kk < GBK; kk++) {
            float4 a0 = *(const float4*)&As[kk][p * 8];
            float4 a1 = *(const float4*)&As[kk][p * 8 + 4];
            const unsigned long long* bp =
                (const unsigned long long*)&Bs[kk][h * 128 + 4 * L];
            unsigned long long b0 = bp[0], b1 = bp[1];
            float av[8] = {a0.x, a0.y, a0.z, a0.w, a1.x, a1.y, a1.z, a1.w};
#pragma unroll
            for (int i = 0; i < 8; i++) {
                unsigned long long ad = bcast2(av[i]);
                fma2(acc[i][0], ad, b0);
                fma2(acc[i][1], ad, b1);
            }
        }
        __syncthreads();
    }

    // ---- epilogue: per-col meta (4 cols) ----
    int cbase = h * 128 + 4 * L;
    float mr[4], bsv[4];
    uint4 wm[4];
#pragma unroll
    for (int j = 0; j < 4; j++) {
        mr[j] = g_mroot1[cbase + j];
        bsv[j] = g_bsum1[cbase + j];
        wm[j] = g_wmask1[cbase + j];
    }
    float v[8][4];
    float s_i[8], q_i[8];
#pragma unroll
    for (int i = 0; i < 8; i++) {
        int row = bm + p * 8 + i;
        float al = g_alpha1[row];
        uint4 mx = g_mask1[row];
        unpack2(acc[i][0], v[i][0], v[i][1]);
        unpack2(acc[i][1], v[i][2], v[i][3]);
        float ss = 0.f, qq = 0.f;
#pragma unroll
        for (int j = 0; j < 4; j++) {
            int pc = popc4(mx, wm[j]);
            float val = v[i][j] + bsv[j] + al * mr[j] * (float)(128 - 2 * pc);
            val = fmaxf(val, 0.f);
            v[i][j] = val;
            ss += val;
            qq = fmaf(val, val, qq);
        }
        s_i[i] = warp_sum(ss);
        q_i[i] = warp_sum(qq);
    }
    if (L == 0)
#pragma unroll
        for (int i = 0; i < 8; i++) redS[p * 8 + i][h] = make_float2(s_i[i], q_i[i]);
    __syncthreads();
    float mu_i[8];
#pragma unroll
    for (int i = 0; i < 8; i++) {
        float2 rA = redS[p * 8 + i][0], rB = redS[p * 8 + i][1];
        mu_i[i] = (rA.x + rB.x) * (1.f / 256.f);
        float l1 = 0.f;
        unsigned bits = 0u;
#pragma unroll
        for (int j = 0; j < 4; j++) {
            float d = v[i][j] - mu_i[i];
            l1 += fabsf(d);
            if (d > 0.f) bits |= 1u << ((L & 7) * 4 + j);
        }
        l1 = warp_sum(l1);
        if (L == 0) redL[p * 8 + i][h] = l1;
        atomicOr(&smask[p * 8 + i][h * 4 + (L >> 3)], bits);
    }
    __syncthreads();
    if (tid < 64) {
        int r = tid;
        float2 rA = redS[r][0], rB = redS[r][1];
        float S = rA.x + rB.x, Q = rA.y + rB.y;
        float mu = S * (1.f / 256.f);
        float var = (Q - 256.f * mu * mu) * (1.f / 255.f);
        float sd = sqrtf(fmaxf(var, 0.f));
        float L1 = redL[r][0] + redL[r][1];
        g_alpha2[bm + r] = (L1 * (1.f / 256.f)) / (sd + EPSV);
        uint4* mp = (uint4*)(g_mask2 + (size_t)(bm + r) * 8);
        mp[0] = make_uint4(smask[r][0], smask[r][1], smask[r][2], smask[r][3]);
        mp[1] = make_uint4(smask[r][4], smask[r][5], smask[r][6], smask[r][7]);
    }
}

// ---------------- fused agg2 + gemm2 + root + log_softmax ----------------
__global__ __launch_bounds__(256) void aggfinal_kernel(float* __restrict__ out) {
    __shared__ float sa[8][264];
    __shared__ float bts[64][72];
    int tid = threadIdx.x;
    int w = tid >> 5, L = tid & 31;
    int d = blockIdx.x * 8 + w;

    unsigned beg = g_off2[d], end = g_off2[d + 1];
    float a[8];
#pragma unroll
    for (int q = 0; q < 8; q++) a[q] = 0.f;
    for (unsigned base = beg; base < end; base += 32u) {
        unsigned e = base + L;
        float al = 0.f;
        uint4 m1 = make_uint4(0u, 0u, 0u, 0u), m2 = m1;
        if (e < end) {
            int s = g_srcs2[e];
            al = g_alpha2[s];
            const uint4* mp = (const uint4*)(g_mask2 + (size_t)s * 8);
            m1 = mp[0]; m2 = mp[1];
        }
        unsigned n = min(32u, end - base);
        for (unsigned t = 0; t < n; t++) {
            float av = __shfl_sync(0xffffffffu, al, t);
            unsigned mw0 = __shfl_sync(0xffffffffu, m1.x, t);
            unsigned mw1 = __shfl_sync(0xffffffffu, m1.y, t);
            unsigned mw2 = __shfl_sync(0xffffffffu, m1.z, t);
            unsigned mw3 = __shfl_sync(0xffffffffu, m1.w, t);
            unsigned mw4 = __shfl_sync(0xffffffffu, m2.x, t);
            unsigned mw5 = __shfl_sync(0xffffffffu, m2.y, t);
            unsigned mw6 = __shfl_sync(0xffffffffu, m2.z, t);
            unsigned mw7 = __shfl_sync(0xffffffffu, m2.w, t);
            a[0] += ((mw0 >> L) & 1u) ? av : -av;
            a[1] += ((mw1 >> L) & 1u) ? av : -av;
            a[2] += ((mw2 >> L) & 1u) ? av : -av;
            a[3] += ((mw3 >> L) & 1u) ? av : -av;
            a[4] += ((mw4 >> L) & 1u) ? av : -av;
            a[5] += ((mw5 >> L) & 1u) ? av : -av;
            a[6] += ((mw6 >> L) & 1u) ? av : -av;
            a[7] += ((mw7 >> L) & 1u) ? av : -av;
        }
    }
    unsigned c = end - beg;
    float inv = 1.f / (float)(c == 0u ? 1u : c);
#pragma unroll
    for (int q = 0; q < 8; q++) sa[w][32 * q + L] = a[q] * inv;  // col = 32q+L

    float acc0 = 0.f, acc1 = 0.f;
    for (int j0 = 0; j0 < HID; j0 += 64) {
        __syncthreads();
#pragma unroll
        for (int r = 0; r < 4; r++) {
            int f = tid + r * 256;
            int jj = f >> 4, c4 = f & 15;
            *(float4*)&bts[jj][c4 * 4] =
                *(const float4*)(g_bt2 + (size_t)(j0 + jj) * OUT_F + 4 * c4);
        }
        __syncthreads();
#pragma unroll 8
        for (int jj = 0; jj < 64; jj++) {
            float av = sa[w][j0 + jj];
            acc0 = fmaf(av, bts[jj][L], acc0);
            acc1 = fmaf(av, bts[jj][L + 32], acc1);
        }
    }

    int c0 = L, c1 = L + 32;
    const uint4* mp = (const uint4*)(g_mask2 + (size_t)d * 8);
    uint4 ma = mp[0], mb = mp[1];
    float al = g_alpha2[d];
    const uint4* w0 = (const uint4*)(g_wmask2 + c0 * 8);
    const uint4* w1 = (const uint4*)(g_wmask2 + c1 * 8);
    int p0 = popc4(ma, w0[0]) + popc4(mb, w0[1]);
    int p1 = popc4(ma, w1[0]) + popc4(mb, w1[1]);
    float v0 = acc0 + g_bsum2[c0] + al * g_mroot2[c0] * (float)(256 - 2 * p0);
    float v1 = acc1 + g_bsum2[c1] + al * g_mroot2[c1] * (float)(256 - 2 * p1);
    float mx = warp_max(fmaxf(v0, v1));
    float s = warp_sum(expf(v0 - mx) + expf(v1 - mx));
    float lse = mx + logf(s);
    out[(size_t)d * OUT_F + c0] = v0 - lse;
    out[(size_t)d * OUT_F + c1] = v1 - lse;
}

// ---------------- launcher ----------------
extern "C" void kernel_launch(void* const* d_in, const int* in_sizes, int n_in,
                              void* d_out, int out_size) {
    const float* x       = (const float*)d_in[0];
    const int*   src1    = (const int*)d_in[1];
    const int*   dst1    = (const int*)d_in[2];
    const int*   src2    = (const int*)d_in[3];
    const int*   dst2    = (const int*)d_in[4];
    const float* w_rel1  = (const float*)d_in[5];
    const float* b_rel1  = (const float*)d_in[6];
    const float* w_root1 = (const float*)d_in[7];
    const float* b_root1 = (const float*)d_in[8];
    const float* w_rel2  = (const float*)d_in[9];
    const float* b_rel2  = (const float*)d_in[10];
    const float* w_root2 = (const float*)d_in[11];
    const float* b_root2 = (const float*)d_in[12];
    float* out = (float*)d_out;

    prep_zero<<<160, 128>>>(w_rel1, w_root1, w_rel2, w_root2,
                            b_rel1, b_root1, b_rel2, b_root2);
    binact1hist_kernel<<<HB + 32000, 512>>>(x, dst1, dst2);
    scan12_kernel<<<2, 1024>>>();
    place12_kernel<<<(NE1 / 4 + NE2 / 4 + 511) / 512, 512>>>(dst1, src1, dst2, src2);
    agg1_kernel<<<NN1 * 32 / 256, 256>>>();
    gemm1_fused_kernel<<<NN1 / 64, 512>>>();
    aggfinal_kernel<<<NN2 / 8, 256>>>(out);
    (void)in_sizes; (void)n_in; (void)out_size;
}